// round 9
// baseline (speedup 1.0000x reference)
#include <cuda_runtime.h>
#include <cuda_bf16.h>
#include <cstdint>
#include <cstddef>

#define NB 8
#define NN 4096
#define NS 1024
#define NK 32
#define NROWS (NB*NS*NK)      // 262144

#define OFF_C1 0
#define OFF_C2 64
#define OFF_W0 192
#define OFF_W1 200
#define OFF_W2 208
#define OFF_LIN 224
#define NSTAT 352
#define EPSBN 1e-5f

// ---------------- scratch ----------------
__device__ float  g_new_xyz[NB*NS*3];
__device__ int    g_nidx[NROWS];
__device__ float  g_off[NROWS*3];
__device__ float  g_Pt[NB*NN*64];
__device__ float  g_z1[(size_t)NROWS*64];
__device__ float  g_z2[(size_t)NROWS*128];
__device__ float  g_zw0[NROWS*8];
__device__ float  g_zw1[NROWS*8];
__device__ float  g_zw2[NROWS*16];
__device__ float  g_feats[(size_t)NB*NS*2048];
__device__ float  g_ypre[NB*NS*128];
__device__ double g_sum[NSTAT];
__device__ double g_sumsq[NSTAT];

// ---------------- helpers ----------------
__device__ __forceinline__ unsigned long long warp_max_ull(unsigned long long v){
#pragma unroll
    for (int o=16;o>0;o>>=1){ unsigned long long u=__shfl_down_sync(0xffffffffu,v,o); if(u>v)v=u; }
    return v;
}
__device__ __forceinline__ unsigned long long warp_min_ull(unsigned long long v){
#pragma unroll
    for (int o=16;o>0;o>>=1){ unsigned long long u=__shfl_down_sync(0xffffffffu,v,o); if(u<v)v=u; }
    return v;
}
__device__ __forceinline__ float2 bn_sf(int off,int c,double n,
                                        const float* __restrict__ gamma,
                                        const float* __restrict__ beta){
    double m  = g_sum[off+c]/n;
    double vv = g_sumsq[off+c]/n - m*m;
    float s = gamma[c]*rsqrtf((float)vv + EPSBN);
    float h = beta[c] - (float)m*s;
    return make_float2(s,h);
}

// ---------------- zero stats ----------------
__global__ void zero_stats_kernel(){
    int t=threadIdx.x;
    if (t<NSTAT){ g_sum[t]=0.0; g_sumsq[t]=0.0; }
}

// ---------------- FPS: one block per batch ----------------
__global__ __launch_bounds__(1024) void fps_kernel(const float* __restrict__ xyz,
                                                   float* __restrict__ out){
    int b=blockIdx.x, t=threadIdx.x;
    const float* xb = xyz + b*3*NN;
    float px[4],py[4],pz[4],dist[4];
#pragma unroll
    for(int j=0;j<4;j++){
        int i=t+j*1024;
        px[j]=xb[i]; py[j]=xb[NN+i]; pz[j]=xb[2*NN+i];
        dist[j]=1e10f;
    }
    __shared__ float cx,cy,cz;
    __shared__ unsigned long long red[32];
    __shared__ int far_sh;
    int wid=t>>5, lane=t&31;

    if (t==0){
        cx=px[0]; cy=py[0]; cz=pz[0];
        g_new_xyz[(b*NS)*3+0]=px[0]; g_new_xyz[(b*NS)*3+1]=py[0]; g_new_xyz[(b*NS)*3+2]=pz[0];
        out[b*3072+0]=px[0]; out[b*3072+1024]=py[0]; out[b*3072+2048]=pz[0];
    }
    __syncthreads();

    for (int k=1;k<NS;k++){
        float lcx=cx,lcy=cy,lcz=cz;
        unsigned long long best=0ull;
#pragma unroll
        for(int j=0;j<4;j++){
            float dx=px[j]-lcx, dy=py[j]-lcy, dz=pz[j]-lcz;
            float d=__fadd_rn(__fadd_rn(__fmul_rn(dx,dx),__fmul_rn(dy,dy)),__fmul_rn(dz,dz));
            dist[j]=fminf(dist[j],d);
            unsigned long long key=((unsigned long long)__float_as_uint(dist[j])<<32)
                                   |(unsigned)(0xFFFFFFFFu-(unsigned)(t+j*1024));
            if(key>best)best=key;
        }
        best=warp_max_ull(best);
        if(lane==0) red[wid]=best;
        __syncthreads();
        if(wid==0){
            unsigned long long v=red[lane];
            v=warp_max_ull(v);
            if(lane==0) far_sh=(int)(0xFFFFFFFFu-(unsigned)(v&0xFFFFFFFFull));
        }
        __syncthreads();
        int far=far_sh;
        if((far&1023)==t){
            int j=far>>10;
            float fx=px[0],fy=py[0],fz=pz[0];
#pragma unroll
            for(int jj=1;jj<4;jj++){ if(j==jj){fx=px[jj];fy=py[jj];fz=pz[jj];} }
            cx=fx; cy=fy; cz=fz;
            g_new_xyz[(b*NS+k)*3+0]=fx; g_new_xyz[(b*NS+k)*3+1]=fy; g_new_xyz[(b*NS+k)*3+2]=fz;
            out[b*3072+k]=fx; out[b*3072+1024+k]=fy; out[b*3072+2048+k]=fz;
        }
        __syncthreads();
    }
}

// ---------------- transpose points [B,64,N] -> [B,N,64] ----------------
__global__ void transpose_kernel(const float* __restrict__ points){
    __shared__ float tile[32][33];
    int b=blockIdx.z, n0=blockIdx.x*32, c0=blockIdx.y*32;
    int tx=threadIdx.x, ty=threadIdx.y;
#pragma unroll
    for(int i=0;i<32;i+=8)
        tile[ty+i][tx]=points[b*64*NN+(c0+ty+i)*NN+n0+tx];
    __syncthreads();
#pragma unroll
    for(int i=0;i<32;i+=8)
        g_Pt[(b*NN+n0+ty+i)*64+c0+tx]=tile[tx][ty+i];
}

// ---------------- kNN ----------------
__device__ __forceinline__ void sort16(unsigned long long k[16]){
#pragma unroll
    for(int size=2;size<=16;size<<=1){
#pragma unroll
        for(int stride=size>>1;stride>0;stride>>=1){
#pragma unroll
            for(int i=0;i<16;i++){
                int j=i^stride;
                if(j>i){
                    bool up=((i&size)==0);
                    unsigned long long a=k[i],bb=k[j];
                    bool sw = up ? (a>bb) : (a<bb);
                    k[i]=sw?bb:a; k[j]=sw?a:bb;
                }
            }
        }
    }
}

__global__ __launch_bounds__(256) void knn_kernel(const float* __restrict__ xyz){
    int q=blockIdx.x, b=q>>10, t=threadIdx.x;
    const float* xb=xyz+b*3*NN;
    float qx=g_new_xyz[q*3], qy=g_new_xyz[q*3+1], qz=g_new_xyz[q*3+2];
    float q2=__fadd_rn(__fadd_rn(__fmul_rn(qx,qx),__fmul_rn(qy,qy)),__fmul_rn(qz,qz));

    unsigned long long key[16];
#pragma unroll
    for(int j=0;j<16;j++){
        int i=j*256+t;
        float x=xb[i], y=xb[NN+i], z=xb[2*NN+i];
        float n2=__fadd_rn(__fadd_rn(__fmul_rn(x,x),__fmul_rn(y,y)),__fmul_rn(z,z));
        float dot=__fadd_rn(__fadd_rn(__fmul_rn(qx,x),__fmul_rn(qy,y)),__fmul_rn(qz,z));
        float d=__fadd_rn(__fadd_rn(__fmul_rn(-2.0f,dot),q2),n2);
        unsigned u=__float_as_uint(d);
        u=(u&0x80000000u)?~u:(u|0x80000000u);
        key[j]=((unsigned long long)u<<32)|(unsigned)i;
    }
    sort16(key);

    __shared__ unsigned long long wmin[8];
    __shared__ unsigned long long winner;
    int wid=t>>5, lane=t&31;
    for(int p=0;p<NK;p++){
        unsigned long long m=warp_min_ull(key[0]);
        if(lane==0) wmin[wid]=m;
        __syncthreads();
        if(t==0){
            unsigned long long mm=wmin[0];
#pragma unroll
            for(int i=1;i<8;i++) if(wmin[i]<mm) mm=wmin[i];
            winner=mm;
            g_nidx[q*NK+p]=(int)(mm&0xFFFFFFFFull);
        }
        __syncthreads();
        unsigned long long w=winner;
        if(key[0]==w){
#pragma unroll
            for(int r=0;r<15;r++) key[r]=key[r+1];
            key[15]=0xFFFFFFFFFFFFFFFFull;
        }
        __syncthreads();
    }
    if(t<NK){
        int n=g_nidx[q*NK+t];
        g_off[(q*NK+t)*3+0]=xb[n]-qx;
        g_off[(q*NK+t)*3+1]=xb[NN+n]-qy;
        g_off[(q*NK+t)*3+2]=xb[2*NN+n]-qz;
    }
}

// ---------------- z1 = gather(P) . c1_w^T + c1_b ----------------
__global__ __launch_bounds__(128) void z1_kernel(const float* __restrict__ W,
                                                 const float* __restrict__ bias){
    __shared__ float Ws[64*64];
    __shared__ float bs[64];
    int t=threadIdx.x;
    for(int i=t;i<4096;i+=128) Ws[i]=W[i];
    if(t<64) bs[t]=bias[t];
    __syncthreads();

    int row=blockIdx.x*128+t;
    int b=row>>15;
    int n=g_nidx[row];
    const float4* src=(const float4*)(g_Pt+((size_t)(b<<12)+n)*64);
    float f[64];
#pragma unroll
    for(int i=0;i<16;i++){ float4 v=src[i]; f[4*i]=v.x; f[4*i+1]=v.y; f[4*i+2]=v.z; f[4*i+3]=v.w; }
    float4* dst=(float4*)(g_z1+(size_t)row*64);
    const float4* W4=(const float4*)Ws;
    for(int c4=0;c4<16;c4++){
        float a0=bs[4*c4],a1=bs[4*c4+1],a2=bs[4*c4+2],a3=bs[4*c4+3];
#pragma unroll
        for(int i=0;i<16;i++){
            float4 w0=W4[(4*c4+0)*16+i], w1=W4[(4*c4+1)*16+i];
            float4 w2=W4[(4*c4+2)*16+i], w3=W4[(4*c4+3)*16+i];
            a0=fmaf(f[4*i],w0.x,fmaf(f[4*i+1],w0.y,fmaf(f[4*i+2],w0.z,fmaf(f[4*i+3],w0.w,a0))));
            a1=fmaf(f[4*i],w1.x,fmaf(f[4*i+1],w1.y,fmaf(f[4*i+2],w1.z,fmaf(f[4*i+3],w1.w,a1))));
            a2=fmaf(f[4*i],w2.x,fmaf(f[4*i+1],w2.y,fmaf(f[4*i+2],w2.z,fmaf(f[4*i+3],w2.w,a2))));
            a3=fmaf(f[4*i],w3.x,fmaf(f[4*i+1],w3.y,fmaf(f[4*i+2],w3.z,fmaf(f[4*i+3],w3.w,a3))));
        }
        dst[c4]=make_float4(a0,a1,a2,a3);
    }
}

// ---------------- z2 = relu(bn1(z1)) . c2_w^T + c2_b ----------------
__global__ __launch_bounds__(128) void z2_kernel(const float* __restrict__ W,
                                                 const float* __restrict__ bias,
                                                 const float* __restrict__ gam,
                                                 const float* __restrict__ bet){
    __shared__ float Ws[128*64];
    __shared__ float bs[128];
    __shared__ float sc[64], sh[64];
    int t=threadIdx.x;
    for(int i=t;i<8192;i+=128) Ws[i]=W[i];
    bs[t]=bias[t];
    if(t<64){ float2 p=bn_sf(OFF_C1,t,262144.0,gam,bet); sc[t]=p.x; sh[t]=p.y; }
    __syncthreads();

    int row=blockIdx.x*128+t;
    const float4* src=(const float4*)(g_z1+(size_t)row*64);
    float a[64];
#pragma unroll
    for(int i=0;i<16;i++){
        float4 v=src[i];
        a[4*i]  =fmaxf(0.f,v.x*sc[4*i]  +sh[4*i]);
        a[4*i+1]=fmaxf(0.f,v.y*sc[4*i+1]+sh[4*i+1]);
        a[4*i+2]=fmaxf(0.f,v.z*sc[4*i+2]+sh[4*i+2]);
        a[4*i+3]=fmaxf(0.f,v.w*sc[4*i+3]+sh[4*i+3]);
    }
    float4* dst=(float4*)(g_z2+(size_t)row*128);
    const float4* W4=(const float4*)Ws;
    for(int c4=0;c4<32;c4++){
        float a0=bs[4*c4],a1=bs[4*c4+1],a2=bs[4*c4+2],a3=bs[4*c4+3];
#pragma unroll
        for(int i=0;i<16;i++){
            float4 w0=W4[(4*c4+0)*16+i], w1=W4[(4*c4+1)*16+i];
            float4 w2=W4[(4*c4+2)*16+i], w3=W4[(4*c4+3)*16+i];
            a0=fmaf(a[4*i],w0.x,fmaf(a[4*i+1],w0.y,fmaf(a[4*i+2],w0.z,fmaf(a[4*i+3],w0.w,a0))));
            a1=fmaf(a[4*i],w1.x,fmaf(a[4*i+1],w1.y,fmaf(a[4*i+2],w1.z,fmaf(a[4*i+3],w1.w,a1))));
            a2=fmaf(a[4*i],w2.x,fmaf(a[4*i+1],w2.y,fmaf(a[4*i+2],w2.z,fmaf(a[4*i+3],w2.w,a2))));
            a3=fmaf(a[4*i],w3.x,fmaf(a[4*i+1],w3.y,fmaf(a[4*i+2],w3.z,fmaf(a[4*i+3],w3.w,a3))));
        }
        dst[c4]=make_float4(a0,a1,a2,a3);
    }
}

// ---------------- WeightNet layers ----------------
__global__ __launch_bounds__(256) void w0_kernel(const float* __restrict__ W,
                                                 const float* __restrict__ bias){
    int r=blockIdx.x*256+threadIdx.x;
    float x=g_off[r*3], y=g_off[r*3+1], z=g_off[r*3+2];
#pragma unroll
    for(int c=0;c<8;c++)
        g_zw0[r*8+c]=fmaf(x,W[c*3],fmaf(y,W[c*3+1],fmaf(z,W[c*3+2],bias[c])));
}

__global__ __launch_bounds__(256) void w1_kernel(const float* __restrict__ W,
                                                 const float* __restrict__ bias,
                                                 const float* __restrict__ gam,
                                                 const float* __restrict__ bet){
    __shared__ float sc[8],sh[8];
    int t=threadIdx.x;
    if(t<8){ float2 p=bn_sf(OFF_W0,t,262144.0,gam,bet); sc[t]=p.x; sh[t]=p.y; }
    __syncthreads();
    int r=blockIdx.x*256+t;
    float a[8];
#pragma unroll
    for(int i=0;i<8;i++) a[i]=fmaxf(0.f,g_zw0[r*8+i]*sc[i]+sh[i]);
#pragma unroll
    for(int c=0;c<8;c++){
        float acc=bias[c];
#pragma unroll
        for(int i=0;i<8;i++) acc=fmaf(a[i],W[c*8+i],acc);
        g_zw1[r*8+c]=acc;
    }
}

__global__ __launch_bounds__(256) void w2_kernel(const float* __restrict__ W,
                                                 const float* __restrict__ bias,
                                                 const float* __restrict__ gam,
                                                 const float* __restrict__ bet){
    __shared__ float sc[8],sh[8];
    int t=threadIdx.x;
    if(t<8){ float2 p=bn_sf(OFF_W1,t,262144.0,gam,bet); sc[t]=p.x; sh[t]=p.y; }
    __syncthreads();
    int r=blockIdx.x*256+t;
    float a[8];
#pragma unroll
    for(int i=0;i<8;i++) a[i]=fmaxf(0.f,g_zw1[r*8+i]*sc[i]+sh[i]);
#pragma unroll
    for(int c=0;c<16;c++){
        float acc=bias[c];
#pragma unroll
        for(int i=0;i<8;i++) acc=fmaf(a[i],W[c*8+i],acc);
        g_zw2[r*16+c]=acc;
    }
}

// ---------------- aggregation: feats[p, c*16+w] = sum_k f*w ----------------
__global__ __launch_bounds__(128) void agg_kernel(const float* __restrict__ g2,
                                                  const float* __restrict__ b2,
                                                  const float* __restrict__ wg,
                                                  const float* __restrict__ wbe){
    __shared__ float wsh[32][16];
    __shared__ float s2s[128],h2s[128],sws[16],hws[16];
    int p=blockIdx.x, t=threadIdx.x;
    { float2 pr=bn_sf(OFF_C2,t,262144.0,g2,b2); s2s[t]=pr.x; h2s[t]=pr.y; }
    if(t<16){ float2 pr=bn_sf(OFF_W2,t,262144.0,wg,wbe); sws[t]=pr.x; hws[t]=pr.y; }
    __syncthreads();
    for(int i=t;i<512;i+=128){
        int k=i>>4, w=i&15;
        float v=g_zw2[(p*32+k)*16+w];
        wsh[k][w]=fmaxf(0.f,v*sws[w]+hws[w]);
    }
    __syncthreads();
    float s2=s2s[t], h2=h2s[t];
    float acc[16];
#pragma unroll
    for(int w=0;w<16;w++) acc[w]=0.f;
    for(int k=0;k<32;k++){
        float fv=fmaxf(0.f,g_z2[((size_t)(p*32+k))*128+t]*s2+h2);
#pragma unroll
        for(int w=0;w<16;w++) acc[w]=fmaf(fv,wsh[k][w],acc[w]);
    }
    float4* d=(float4*)(g_feats+(size_t)p*2048+t*16);
#pragma unroll
    for(int w4=0;w4<4;w4++)
        d[w4]=make_float4(acc[4*w4],acc[4*w4+1],acc[4*w4+2],acc[4*w4+3]);
}

// ---------------- final GEMM: ypre = feats @ lin_w^T + lin_b ----------------
__global__ __launch_bounds__(256) void lin_kernel(const float* __restrict__ W,
                                                  const float* __restrict__ bias){
    __shared__ float As[64][33];
    __shared__ float Bs[64][33];
    int t=threadIdx.x;
    int row0=blockIdx.x*64, col0=blockIdx.y*64;
    int tx=t&31, ty=t>>5;     // loads: 32x8
    int tr=t>>4, tc=t&15;     // compute: 16x16, 4x4 each
    float acc[4][4];
#pragma unroll
    for(int j=0;j<4;j++)
#pragma unroll
        for(int jj=0;jj<4;jj++) acc[j][jj]=0.f;

    for(int k0=0;k0<2048;k0+=32){
#pragma unroll
        for(int i=0;i<64;i+=8)
            As[ty+i][tx]=g_feats[(size_t)(row0+ty+i)*2048+k0+tx];
#pragma unroll
        for(int i=0;i<64;i+=8)
            Bs[ty+i][tx]=W[(size_t)(col0+ty+i)*2048+k0+tx];
        __syncthreads();
#pragma unroll
        for(int kk=0;kk<32;kk++){
            float ra[4],rb[4];
#pragma unroll
            for(int j=0;j<4;j++){ ra[j]=As[tr*4+j][kk]; rb[j]=Bs[tc*4+j][kk]; }
#pragma unroll
            for(int j=0;j<4;j++)
#pragma unroll
                for(int jj=0;jj<4;jj++) acc[j][jj]=fmaf(ra[j],rb[jj],acc[j][jj]);
        }
        __syncthreads();
    }
#pragma unroll
    for(int j=0;j<4;j++)
#pragma unroll
        for(int jj=0;jj<4;jj++)
            g_ypre[(size_t)(row0+tr*4+j)*128+col0+tc*4+jj]=acc[j][jj]+bias[col0+tc*4+jj];
}

// ---------------- generic channel stats ----------------
__global__ __launch_bounds__(256) void stats_kernel(const float* __restrict__ data,
                                                    int cols,int off,int rpb){
    int t=threadIdx.x;
    int ch=t%cols;
    int rstep=256/cols;
    double s=0.0, ss=0.0;
    size_t base=(size_t)blockIdx.x*rpb;
    for(int r=t/cols;r<rpb;r+=rstep){
        float v=data[(base+r)*(size_t)cols+ch];
        s+=v; ss+=(double)v*v;
    }
    atomicAdd(&g_sum[off+ch],s);
    atomicAdd(&g_sumsq[off+ch],ss);
}

// ---------------- output: y = relu(bn(ypre)) transposed ----------------
__global__ void outy_kernel(const float* __restrict__ lg,
                            const float* __restrict__ lb,
                            float* __restrict__ out){
    __shared__ float tile[32][33];
    __shared__ float s[32],h[32];
    int b=blockIdx.z, s0=blockIdx.x*32, c0=blockIdx.y*32;
    int tx=threadIdx.x, ty=threadIdx.y;
    if(ty==0){ float2 p=bn_sf(OFF_LIN,c0+tx,8192.0,lg,lb); s[tx]=p.x; h[tx]=p.y; }
    __syncthreads();
#pragma unroll
    for(int i=0;i<32;i+=8){
        float v=g_ypre[(size_t)(b*1024+s0+ty+i)*128+c0+tx];
        tile[ty+i][tx]=fmaxf(0.f,v*s[tx]+h[tx]);
    }
    __syncthreads();
    float* y=out+24576;
#pragma unroll
    for(int i=0;i<32;i+=8)
        y[(size_t)b*131072+(c0+ty+i)*1024+s0+tx]=tile[tx][ty+i];
}

// ---------------- launch ----------------
extern "C" void kernel_launch(void* const* d_in, const int* in_sizes, int n_in,
                              void* d_out, int out_size){
    const float* xyz   =(const float*)d_in[0];
    const float* points=(const float*)d_in[1];
    const float* c1_w=(const float*)d_in[2];  const float* c1_b=(const float*)d_in[3];
    const float* g1  =(const float*)d_in[4];  const float* b1  =(const float*)d_in[5];
    const float* c2_w=(const float*)d_in[6];  const float* c2_b=(const float*)d_in[7];
    const float* g2  =(const float*)d_in[8];  const float* b2  =(const float*)d_in[9];
    const float* w0_w=(const float*)d_in[10]; const float* w0_b=(const float*)d_in[11];
    const float* w0_g=(const float*)d_in[12]; const float* w0_be=(const float*)d_in[13];
    const float* w1_w=(const float*)d_in[14]; const float* w1_b=(const float*)d_in[15];
    const float* w1_g=(const float*)d_in[16]; const float* w1_be=(const float*)d_in[17];
    const float* w2_w=(const float*)d_in[18]; const float* w2_b=(const float*)d_in[19];
    const float* w2_g=(const float*)d_in[20]; const float* w2_be=(const float*)d_in[21];
    const float* lin_w=(const float*)d_in[22];const float* lin_b=(const float*)d_in[23];
    const float* lg  =(const float*)d_in[24]; const float* lb  =(const float*)d_in[25];
    float* out=(float*)d_out;

    float *z1p,*z2p,*w0p,*w1p,*w2p,*yp;
    cudaGetSymbolAddress((void**)&z1p,g_z1);
    cudaGetSymbolAddress((void**)&z2p,g_z2);
    cudaGetSymbolAddress((void**)&w0p,g_zw0);
    cudaGetSymbolAddress((void**)&w1p,g_zw1);
    cudaGetSymbolAddress((void**)&w2p,g_zw2);
    cudaGetSymbolAddress((void**)&yp, g_ypre);

    zero_stats_kernel<<<1,512>>>();
    fps_kernel<<<NB,1024>>>(xyz,out);
    transpose_kernel<<<dim3(NN/32,2,NB),dim3(32,8)>>>(points);
    knn_kernel<<<NB*NS,256>>>(xyz);

    z1_kernel<<<NROWS/128,128>>>(c1_w,c1_b);
    stats_kernel<<<256,256>>>(z1p,64,OFF_C1,1024);
    z2_kernel<<<NROWS/128,128>>>(c2_w,c2_b,g1,b1);
    stats_kernel<<<256,256>>>(z2p,128,OFF_C2,1024);

    w0_kernel<<<NROWS/256,256>>>(w0_w,w0_b);
    stats_kernel<<<256,256>>>(w0p,8,OFF_W0,1024);
    w1_kernel<<<NROWS/256,256>>>(w1_w,w1_b,w0_g,w0_be);
    stats_kernel<<<256,256>>>(w1p,8,OFF_W1,1024);
    w2_kernel<<<NROWS/256,256>>>(w2_w,w2_b,w1_g,w1_be);
    stats_kernel<<<256,256>>>(w2p,16,OFF_W2,1024);

    agg_kernel<<<NB*NS,128>>>(g2,b2,w2_g,w2_be);
    lin_kernel<<<dim3(128,2),256>>>(lin_w,lin_b);
    stats_kernel<<<64,256>>>(yp,128,OFF_LIN,128);
    outy_kernel<<<dim3(32,4,NB),dim3(32,8)>>>(lg,lb,out);
}

// round 10
// speedup vs baseline: 1.0536x; 1.0536x over previous
#include <cuda_runtime.h>
#include <cuda_bf16.h>
#include <cstdint>
#include <cstddef>

#define NB 8
#define NN 4096
#define NS 1024
#define NK 32
#define NROWS (NB*NS*NK)      // 262144

#define OFF_C1 0
#define OFF_C2 64
#define OFF_W0 192
#define OFF_W1 200
#define OFF_W2 208
#define OFF_LIN 224
#define NSTAT 352
#define EPSBN 1e-5f

// ---------------- scratch ----------------
__device__ float  g_new_xyz[NB*NS*3];
__device__ int    g_nidx[NROWS];
__device__ float  g_off[NROWS*3];
__device__ float  g_Pt[NB*NN*64];
__device__ float  g_z1[(size_t)NROWS*64];
__device__ float  g_z2[(size_t)NROWS*128];
__device__ float  g_zw0[NROWS*8];
__device__ float  g_zw1[NROWS*8];
__device__ float  g_zw2[NROWS*16];
__device__ float  g_feats[(size_t)NB*NS*2048];
__device__ float  g_ypre[NB*NS*128];
__device__ double g_sum[NSTAT];
__device__ double g_sumsq[NSTAT];

// ---------------- helpers ----------------
__device__ __forceinline__ unsigned long long warp_max_ull(unsigned long long v){
#pragma unroll
    for (int o=16;o>0;o>>=1){ unsigned long long u=__shfl_down_sync(0xffffffffu,v,o); if(u>v)v=u; }
    return v;
}
__device__ __forceinline__ float2 bn_sf(int off,int c,double n,
                                        const float* __restrict__ gamma,
                                        const float* __restrict__ beta){
    double m  = g_sum[off+c]/n;
    double vv = g_sumsq[off+c]/n - m*m;
    float s = gamma[c]*rsqrtf((float)vv + EPSBN);
    float h = beta[c] - (float)m*s;
    return make_float2(s,h);
}

// ---------------- zero stats ----------------
__global__ void zero_stats_kernel(){
    int t=threadIdx.x;
    if (t<NSTAT){ g_sum[t]=0.0; g_sumsq[t]=0.0; }
}

// ---------------- FPS: one block per batch ----------------
__global__ __launch_bounds__(1024) void fps_kernel(const float* __restrict__ xyz,
                                                   float* __restrict__ out){
    int b=blockIdx.x, t=threadIdx.x;
    const float* xb = xyz + b*3*NN;
    float px[4],py[4],pz[4],dist[4];
#pragma unroll
    for(int j=0;j<4;j++){
        int i=t+j*1024;
        px[j]=xb[i]; py[j]=xb[NN+i]; pz[j]=xb[2*NN+i];
        dist[j]=1e10f;
    }
    __shared__ float cx,cy,cz;
    __shared__ unsigned long long red[32];
    __shared__ int far_sh;
    int wid=t>>5, lane=t&31;

    if (t==0){
        cx=px[0]; cy=py[0]; cz=pz[0];
        g_new_xyz[(b*NS)*3+0]=px[0]; g_new_xyz[(b*NS)*3+1]=py[0]; g_new_xyz[(b*NS)*3+2]=pz[0];
        out[b*3072+0]=px[0]; out[b*3072+1024]=py[0]; out[b*3072+2048]=pz[0];
    }
    __syncthreads();

    for (int k=1;k<NS;k++){
        float lcx=cx,lcy=cy,lcz=cz;
        unsigned long long best=0ull;
#pragma unroll
        for(int j=0;j<4;j++){
            float dx=px[j]-lcx, dy=py[j]-lcy, dz=pz[j]-lcz;
            float d=__fadd_rn(__fadd_rn(__fmul_rn(dx,dx),__fmul_rn(dy,dy)),__fmul_rn(dz,dz));
            dist[j]=fminf(dist[j],d);
            unsigned long long key=((unsigned long long)__float_as_uint(dist[j])<<32)
                                   |(unsigned)(0xFFFFFFFFu-(unsigned)(t+j*1024));
            if(key>best)best=key;
        }
        best=warp_max_ull(best);
        if(lane==0) red[wid]=best;
        __syncthreads();
        if(wid==0){
            unsigned long long v=red[lane];
            v=warp_max_ull(v);
            if(lane==0) far_sh=(int)(0xFFFFFFFFu-(unsigned)(v&0xFFFFFFFFull));
        }
        __syncthreads();
        int far=far_sh;
        if((far&1023)==t){
            int j=far>>10;
            float fx=px[0],fy=py[0],fz=pz[0];
#pragma unroll
            for(int jj=1;jj<4;jj++){ if(j==jj){fx=px[jj];fy=py[jj];fz=pz[jj];} }
            cx=fx; cy=fy; cz=fz;
            g_new_xyz[(b*NS+k)*3+0]=fx; g_new_xyz[(b*NS+k)*3+1]=fy; g_new_xyz[(b*NS+k)*3+2]=fz;
            out[b*3072+k]=fx; out[b*3072+1024+k]=fy; out[b*3072+2048+k]=fz;
        }
        __syncthreads();
    }
}

// ---------------- transpose points [B,64,N] -> [B,N,64] ----------------
__global__ void transpose_kernel(const float* __restrict__ points){
    __shared__ float tile[32][33];
    int b=blockIdx.z, n0=blockIdx.x*32, c0=blockIdx.y*32;
    int tx=threadIdx.x, ty=threadIdx.y;
#pragma unroll
    for(int i=0;i<32;i+=8)
        tile[ty+i][tx]=points[b*64*NN+(c0+ty+i)*NN+n0+tx];
    __syncthreads();
#pragma unroll
    for(int i=0;i<32;i+=8)
        g_Pt[(b*NN+n0+ty+i)*64+c0+tx]=tile[tx][ty+i];
}

// ---------------- kNN: exact top-32 via 8-bit MSB radix select ----------------
// Set semantics only (downstream is order-invariant): emit all keys with
// dist-bits < T unordered, then the R smallest-index keys among dist-bits == T.
__global__ __launch_bounds__(256) void knn_kernel(const float* __restrict__ xyz){
    int q=blockIdx.x, b=q>>10, t=threadIdx.x;
    const float* xb=xyz+b*3*NN;
    float qx=g_new_xyz[q*3], qy=g_new_xyz[q*3+1], qz=g_new_xyz[q*3+2];
    float q2=__fadd_rn(__fadd_rn(__fmul_rn(qx,qx),__fmul_rn(qy,qy)),__fmul_rn(qz,qz));

    unsigned dk[16];
#pragma unroll
    for(int j=0;j<16;j++){
        int i=j*256+t;
        float x=xb[i], y=xb[NN+i], z=xb[2*NN+i];
        float n2=__fadd_rn(__fadd_rn(__fmul_rn(x,x),__fmul_rn(y,y)),__fmul_rn(z,z));
        float dot=__fadd_rn(__fadd_rn(__fmul_rn(qx,x),__fmul_rn(qy,y)),__fmul_rn(qz,z));
        float d=__fadd_rn(__fadd_rn(__fmul_rn(-2.0f,dot),q2),n2);
        unsigned u=__float_as_uint(d);
        dk[j]=(u&0x80000000u)?~u:(u|0x80000000u);   // order-preserving transform
    }

    __shared__ unsigned hist[256];
    __shared__ unsigned sh_d, sh_cb;
    __shared__ unsigned cnt, tcnt;
    __shared__ unsigned ties[256];

    unsigned prefix=0, R=32;
#pragma unroll
    for(int shift=24;shift>=0;shift-=8){
        hist[t]=0;
        __syncthreads();
        unsigned mask_hi=(shift==24)?0u:(0xFFFFFFFFu<<(shift+8));
#pragma unroll
        for(int j=0;j<16;j++){
            if((dk[j]&mask_hi)==prefix)
                atomicAdd(&hist[(dk[j]>>shift)&0xFFu],1u);
        }
        __syncthreads();
        if(t<32){
            unsigned s=0;
#pragma unroll
            for(int i=0;i<8;i++) s+=hist[t*8+i];
            unsigned v=s;
#pragma unroll
            for(int o=1;o<32;o<<=1){ unsigned u=__shfl_up_sync(0xffffffffu,v,o); if(t>=o) v+=u; }
            unsigned cum=v-s;                       // exclusive base for this lane
            unsigned cand=0xFFFFFFFFu;
#pragma unroll
            for(int i=0;i<8;i++){
                unsigned h=hist[t*8+i];
                if(cand==0xFFFFFFFFu && cum+h>=R) cand=((unsigned)(t*8+i)<<16)|cum;
                cum+=h;
            }
#pragma unroll
            for(int o=16;o>0;o>>=1){ unsigned u=__shfl_down_sync(0xffffffffu,cand,o); if(u<cand)cand=u; }
            if(t==0){ sh_d=cand>>16; sh_cb=cand&0xFFFFu; }
        }
        __syncthreads();
        prefix|=sh_d<<shift;
        R-=sh_cb;
    }
    unsigned T=prefix;              // dist-bits of the 32nd smallest key
    if(t==0){ cnt=0; tcnt=0; }
    __syncthreads();
#pragma unroll
    for(int j=0;j<16;j++){
        unsigned key=dk[j];
        unsigned idx=(unsigned)(j*256+t);
        if(key<T){
            unsigned p=atomicAdd(&cnt,1u);
            g_nidx[q*NK+p]=(int)idx;
        } else if(key==T){
            unsigned p=atomicAdd(&tcnt,1u);
            if(p<256u) ties[p]=idx;
        }
    }
    __syncthreads();
    if(t==0){
        unsigned n=cnt;                      // == 32 - R
        unsigned L=tcnt<256u?tcnt:256u;
        for(unsigned r=0;r<R;r++){
            unsigned mi=0xFFFFFFFFu, mp=0;
            for(unsigned i=0;i<L;i++) if(ties[i]<mi){mi=ties[i];mp=i;}
            g_nidx[q*NK+n+r]=(int)mi;
            ties[mp]=0xFFFFFFFFu;
        }
    }
    __syncthreads();
    if(t<NK){
        int n=g_nidx[q*NK+t];
        g_off[(q*NK+t)*3+0]=xb[n]-qx;
        g_off[(q*NK+t)*3+1]=xb[NN+n]-qy;
        g_off[(q*NK+t)*3+2]=xb[2*NN+n]-qz;
    }
}

// ---------------- z1 = gather(P) . c1_w^T + c1_b ----------------
__global__ __launch_bounds__(128) void z1_kernel(const float* __restrict__ W,
                                                 const float* __restrict__ bias){
    __shared__ float Ws[64*64];
    __shared__ float bs[64];
    int t=threadIdx.x;
    for(int i=t;i<4096;i+=128) Ws[i]=W[i];
    if(t<64) bs[t]=bias[t];
    __syncthreads();

    int row=blockIdx.x*128+t;
    int b=row>>15;
    int n=g_nidx[row];
    const float4* src=(const float4*)(g_Pt+((size_t)(b<<12)+n)*64);
    float f[64];
#pragma unroll
    for(int i=0;i<16;i++){ float4 v=src[i]; f[4*i]=v.x; f[4*i+1]=v.y; f[4*i+2]=v.z; f[4*i+3]=v.w; }
    float4* dst=(float4*)(g_z1+(size_t)row*64);
    const float4* W4=(const float4*)Ws;
    for(int c4=0;c4<16;c4++){
        float a0=bs[4*c4],a1=bs[4*c4+1],a2=bs[4*c4+2],a3=bs[4*c4+3];
#pragma unroll
        for(int i=0;i<16;i++){
            float4 w0=W4[(4*c4+0)*16+i], w1=W4[(4*c4+1)*16+i];
            float4 w2=W4[(4*c4+2)*16+i], w3=W4[(4*c4+3)*16+i];
            a0=fmaf(f[4*i],w0.x,fmaf(f[4*i+1],w0.y,fmaf(f[4*i+2],w0.z,fmaf(f[4*i+3],w0.w,a0))));
            a1=fmaf(f[4*i],w1.x,fmaf(f[4*i+1],w1.y,fmaf(f[4*i+2],w1.z,fmaf(f[4*i+3],w1.w,a1))));
            a2=fmaf(f[4*i],w2.x,fmaf(f[4*i+1],w2.y,fmaf(f[4*i+2],w2.z,fmaf(f[4*i+3],w2.w,a2))));
            a3=fmaf(f[4*i],w3.x,fmaf(f[4*i+1],w3.y,fmaf(f[4*i+2],w3.z,fmaf(f[4*i+3],w3.w,a3))));
        }
        dst[c4]=make_float4(a0,a1,a2,a3);
    }
}

// ---------------- z2 = relu(bn1(z1)) . c2_w^T + c2_b ----------------
__global__ __launch_bounds__(128) void z2_kernel(const float* __restrict__ W,
                                                 const float* __restrict__ bias,
                                                 const float* __restrict__ gam,
                                                 const float* __restrict__ bet){
    __shared__ float Ws[128*64];
    __shared__ float bs[128];
    __shared__ float sc[64], sh[64];
    int t=threadIdx.x;
    for(int i=t;i<8192;i+=128) Ws[i]=W[i];
    bs[t]=bias[t];
    if(t<64){ float2 p=bn_sf(OFF_C1,t,262144.0,gam,bet); sc[t]=p.x; sh[t]=p.y; }
    __syncthreads();

    int row=blockIdx.x*128+t;
    const float4* src=(const float4*)(g_z1+(size_t)row*64);
    float a[64];
#pragma unroll
    for(int i=0;i<16;i++){
        float4 v=src[i];
        a[4*i]  =fmaxf(0.f,v.x*sc[4*i]  +sh[4*i]);
        a[4*i+1]=fmaxf(0.f,v.y*sc[4*i+1]+sh[4*i+1]);
        a[4*i+2]=fmaxf(0.f,v.z*sc[4*i+2]+sh[4*i+2]);
        a[4*i+3]=fmaxf(0.f,v.w*sc[4*i+3]+sh[4*i+3]);
    }
    float4* dst=(float4*)(g_z2+(size_t)row*128);
    const float4* W4=(const float4*)Ws;
    for(int c4=0;c4<32;c4++){
        float a0=bs[4*c4],a1=bs[4*c4+1],a2=bs[4*c4+2],a3=bs[4*c4+3];
#pragma unroll
        for(int i=0;i<16;i++){
            float4 w0=W4[(4*c4+0)*16+i], w1=W4[(4*c4+1)*16+i];
            float4 w2=W4[(4*c4+2)*16+i], w3=W4[(4*c4+3)*16+i];
            a0=fmaf(a[4*i],w0.x,fmaf(a[4*i+1],w0.y,fmaf(a[4*i+2],w0.z,fmaf(a[4*i+3],w0.w,a0))));
            a1=fmaf(a[4*i],w1.x,fmaf(a[4*i+1],w1.y,fmaf(a[4*i+2],w1.z,fmaf(a[4*i+3],w1.w,a1))));
            a2=fmaf(a[4*i],w2.x,fmaf(a[4*i+1],w2.y,fmaf(a[4*i+2],w2.z,fmaf(a[4*i+3],w2.w,a2))));
            a3=fmaf(a[4*i],w3.x,fmaf(a[4*i+1],w3.y,fmaf(a[4*i+2],w3.z,fmaf(a[4*i+3],w3.w,a3))));
        }
        dst[c4]=make_float4(a0,a1,a2,a3);
    }
}

// ---------------- WeightNet layers ----------------
__global__ __launch_bounds__(256) void w0_kernel(const float* __restrict__ W,
                                                 const float* __restrict__ bias){
    int r=blockIdx.x*256+threadIdx.x;
    float x=g_off[r*3], y=g_off[r*3+1], z=g_off[r*3+2];
#pragma unroll
    for(int c=0;c<8;c++)
        g_zw0[r*8+c]=fmaf(x,W[c*3],fmaf(y,W[c*3+1],fmaf(z,W[c*3+2],bias[c])));
}

__global__ __launch_bounds__(256) void w1_kernel(const float* __restrict__ W,
                                                 const float* __restrict__ bias,
                                                 const float* __restrict__ gam,
                                                 const float* __restrict__ bet){
    __shared__ float sc[8],sh[8];
    int t=threadIdx.x;
    if(t<8){ float2 p=bn_sf(OFF_W0,t,262144.0,gam,bet); sc[t]=p.x; sh[t]=p.y; }
    __syncthreads();
    int r=blockIdx.x*256+t;
    float a[8];
#pragma unroll
    for(int i=0;i<8;i++) a[i]=fmaxf(0.f,g_zw0[r*8+i]*sc[i]+sh[i]);
#pragma unroll
    for(int c=0;c<8;c++){
        float acc=bias[c];
#pragma unroll
        for(int i=0;i<8;i++) acc=fmaf(a[i],W[c*8+i],acc);
        g_zw1[r*8+c]=acc;
    }
}

__global__ __launch_bounds__(256) void w2_kernel(const float* __restrict__ W,
                                                 const float* __restrict__ bias,
                                                 const float* __restrict__ gam,
                                                 const float* __restrict__ bet){
    __shared__ float sc[8],sh[8];
    int t=threadIdx.x;
    if(t<8){ float2 p=bn_sf(OFF_W1,t,262144.0,gam,bet); sc[t]=p.x; sh[t]=p.y; }
    __syncthreads();
    int r=blockIdx.x*256+t;
    float a[8];
#pragma unroll
    for(int i=0;i<8;i++) a[i]=fmaxf(0.f,g_zw1[r*8+i]*sc[i]+sh[i]);
#pragma unroll
    for(int c=0;c<16;c++){
        float acc=bias[c];
#pragma unroll
        for(int i=0;i<8;i++) acc=fmaf(a[i],W[c*8+i],acc);
        g_zw2[r*16+c]=acc;
    }
}

// ---------------- aggregation: feats[p, c*16+w] = sum_k f*w ----------------
__global__ __launch_bounds__(128) void agg_kernel(const float* __restrict__ g2,
                                                  const float* __restrict__ b2,
                                                  const float* __restrict__ wg,
                                                  const float* __restrict__ wbe){
    __shared__ float wsh[32][16];
    __shared__ float s2s[128],h2s[128],sws[16],hws[16];
    int p=blockIdx.x, t=threadIdx.x;
    { float2 pr=bn_sf(OFF_C2,t,262144.0,g2,b2); s2s[t]=pr.x; h2s[t]=pr.y; }
    if(t<16){ float2 pr=bn_sf(OFF_W2,t,262144.0,wg,wbe); sws[t]=pr.x; hws[t]=pr.y; }
    __syncthreads();
    for(int i=t;i<512;i+=128){
        int k=i>>4, w=i&15;
        float v=g_zw2[(p*32+k)*16+w];
        wsh[k][w]=fmaxf(0.f,v*sws[w]+hws[w]);
    }
    __syncthreads();
    float s2=s2s[t], h2=h2s[t];
    float acc[16];
#pragma unroll
    for(int w=0;w<16;w++) acc[w]=0.f;
    for(int k=0;k<32;k++){
        float fv=fmaxf(0.f,g_z2[((size_t)(p*32+k))*128+t]*s2+h2);
#pragma unroll
        for(int w=0;w<16;w++) acc[w]=fmaf(fv,wsh[k][w],acc[w]);
    }
    float4* d=(float4*)(g_feats+(size_t)p*2048+t*16);
#pragma unroll
    for(int w4=0;w4<4;w4++)
        d[w4]=make_float4(acc[4*w4],acc[4*w4+1],acc[4*w4+2],acc[4*w4+3]);
}

// ---------------- final GEMM: ypre = feats @ lin_w^T + lin_b ----------------
// 64x128 tile per block, k-major smem, float4 fragments, register prefetch.
__global__ __launch_bounds__(256) void lin_kernel(const float* __restrict__ W,
                                                  const float* __restrict__ bias){
    __shared__ float As[32][68];   // [k][m], row stride 272B (16B aligned)
    __shared__ float Bs[32][132];  // [k][n], row stride 528B (16B aligned)
    int t=threadIdx.x;
    int row0=blockIdx.x*64;
    int lk=(t&7)*4;       // k offset within stage: 0,4,...,28
    int lr=t>>3;          // 0..31
    int tr=t>>4;          // 0..15 -> rows tr*4..tr*4+3
    int tc=t&15;          // 0..15 -> cols tc*8..tc*8+7

    const float* pA0=g_feats+(size_t)(row0+lr)*2048+lk;
    const float* pA1=g_feats+(size_t)(row0+lr+32)*2048+lk;
    const float* pB0=W+(size_t)lr*2048+lk;
    const float* pB1=W+(size_t)(lr+32)*2048+lk;
    const float* pB2=W+(size_t)(lr+64)*2048+lk;
    const float* pB3=W+(size_t)(lr+96)*2048+lk;

    float4 a0=*(const float4*)pA0, a1=*(const float4*)pA1;
    float4 b0=*(const float4*)pB0, b1=*(const float4*)pB1;
    float4 b2=*(const float4*)pB2, b3=*(const float4*)pB3;

    float acc[4][8];
#pragma unroll
    for(int j=0;j<4;j++)
#pragma unroll
        for(int jj=0;jj<8;jj++) acc[j][jj]=0.f;

    for(int k0=0;k0<2048;k0+=32){
        As[lk+0][lr]=a0.x; As[lk+1][lr]=a0.y; As[lk+2][lr]=a0.z; As[lk+3][lr]=a0.w;
        As[lk+0][lr+32]=a1.x; As[lk+1][lr+32]=a1.y; As[lk+2][lr+32]=a1.z; As[lk+3][lr+32]=a1.w;
        Bs[lk+0][lr]=b0.x; Bs[lk+1][lr]=b0.y; Bs[lk+2][lr]=b0.z; Bs[lk+3][lr]=b0.w;
        Bs[lk+0][lr+32]=b1.x; Bs[lk+1][lr+32]=b1.y; Bs[lk+2][lr+32]=b1.z; Bs[lk+3][lr+32]=b1.w;
        Bs[lk+0][lr+64]=b2.x; Bs[lk+1][lr+64]=b2.y; Bs[lk+2][lr+64]=b2.z; Bs[lk+3][lr+64]=b2.w;
        Bs[lk+0][lr+96]=b3.x; Bs[lk+1][lr+96]=b3.y; Bs[lk+2][lr+96]=b3.z; Bs[lk+3][lr+96]=b3.w;
        __syncthreads();
        if(k0+32<2048){
            int o=k0+32;
            a0=*(const float4*)(pA0+o); a1=*(const float4*)(pA1+o);
            b0=*(const float4*)(pB0+o); b1=*(const float4*)(pB1+o);
            b2=*(const float4*)(pB2+o); b3=*(const float4*)(pB3+o);
        }
#pragma unroll
        for(int kk=0;kk<32;kk++){
            float4 ra =*(const float4*)&As[kk][tr*4];
            float4 rb0=*(const float4*)&Bs[kk][tc*8];
            float4 rb1=*(const float4*)&Bs[kk][tc*8+4];
            float ar[4]={ra.x,ra.y,ra.z,ra.w};
            float br[8]={rb0.x,rb0.y,rb0.z,rb0.w,rb1.x,rb1.y,rb1.z,rb1.w};
#pragma unroll
            for(int j=0;j<4;j++)
#pragma unroll
                for(int jj=0;jj<8;jj++) acc[j][jj]=fmaf(ar[j],br[jj],acc[j][jj]);
        }
        __syncthreads();
    }
#pragma unroll
    for(int j=0;j<4;j++)
#pragma unroll
        for(int jj=0;jj<8;jj++)
            g_ypre[(size_t)(row0+tr*4+j)*128+tc*8+jj]=acc[j][jj]+bias[tc*8+jj];
}

// ---------------- generic channel stats ----------------
__global__ __launch_bounds__(256) void stats_kernel(const float* __restrict__ data,
                                                    int cols,int off,int rpb){
    int t=threadIdx.x;
    int ch=t%cols;
    int rstep=256/cols;
    double s=0.0, ss=0.0;
    size_t base=(size_t)blockIdx.x*rpb;
    for(int r=t/cols;r<rpb;r+=rstep){
        float v=data[(base+r)*(size_t)cols+ch];
        s+=v; ss+=(double)v*v;
    }
    atomicAdd(&g_sum[off+ch],s);
    atomicAdd(&g_sumsq[off+ch],ss);
}

// ---------------- output: y = relu(bn(ypre)) transposed ----------------
__global__ void outy_kernel(const float* __restrict__ lg,
                            const float* __restrict__ lb,
                            float* __restrict__ out){
    __shared__ float tile[32][33];
    __shared__ float s[32],h[32];
    int b=blockIdx.z, s0=blockIdx.x*32, c0=blockIdx.y*32;
    int tx=threadIdx.x, ty=threadIdx.y;
    if(ty==0){ float2 p=bn_sf(OFF_LIN,c0+tx,8192.0,lg,lb); s[tx]=p.x; h[tx]=p.y; }
    __syncthreads();
#pragma unroll
    for(int i=0;i<32;i+=8){
        float v=g_ypre[(size_t)(b*1024+s0+ty+i)*128+c0+tx];
        tile[ty+i][tx]=fmaxf(0.f,v*s[tx]+h[tx]);
    }
    __syncthreads();
    float* y=out+24576;
#pragma unroll
    for(int i=0;i<32;i+=8)
        y[(size_t)b*131072+(c0+ty+i)*1024+s0+tx]=tile[tx][ty+i];
}

// ---------------- launch ----------------
extern "C" void kernel_launch(void* const* d_in, const int* in_sizes, int n_in,
                              void* d_out, int out_size){
    const float* xyz   =(const float*)d_in[0];
    const float* points=(const float*)d_in[1];
    const float* c1_w=(const float*)d_in[2];  const float* c1_b=(const float*)d_in[3];
    const float* g1  =(const float*)d_in[4];  const float* b1  =(const float*)d_in[5];
    const float* c2_w=(const float*)d_in[6];  const float* c2_b=(const float*)d_in[7];
    const float* g2  =(const float*)d_in[8];  const float* b2  =(const float*)d_in[9];
    const float* w0_w=(const float*)d_in[10]; const float* w0_b=(const float*)d_in[11];
    const float* w0_g=(const float*)d_in[12]; const float* w0_be=(const float*)d_in[13];
    const float* w1_w=(const float*)d_in[14]; const float* w1_b=(const float*)d_in[15];
    const float* w1_g=(const float*)d_in[16]; const float* w1_be=(const float*)d_in[17];
    const float* w2_w=(const float*)d_in[18]; const float* w2_b=(const float*)d_in[19];
    const float* w2_g=(const float*)d_in[20]; const float* w2_be=(const float*)d_in[21];
    const float* lin_w=(const float*)d_in[22];const float* lin_b=(const float*)d_in[23];
    const float* lg  =(const float*)d_in[24]; const float* lb  =(const float*)d_in[25];
    float* out=(float*)d_out;

    float *z1p,*z2p,*w0p,*w1p,*w2p,*yp;
    cudaGetSymbolAddress((void**)&z1p,g_z1);
    cudaGetSymbolAddress((void**)&z2p,g_z2);
    cudaGetSymbolAddress((void**)&w0p,g_zw0);
    cudaGetSymbolAddress((void**)&w1p,g_zw1);
    cudaGetSymbolAddress((void**)&w2p,g_zw2);
    cudaGetSymbolAddress((void**)&yp, g_ypre);

    zero_stats_kernel<<<1,512>>>();
    fps_kernel<<<NB,1024>>>(xyz,out);
    transpose_kernel<<<dim3(NN/32,2,NB),dim3(32,8)>>>(points);
    knn_kernel<<<NB*NS,256>>>(xyz);

    z1_kernel<<<NROWS/128,128>>>(c1_w,c1_b);
    stats_kernel<<<256,256>>>(z1p,64,OFF_C1,1024);
    z2_kernel<<<NROWS/128,128>>>(c2_w,c2_b,g1,b1);
    stats_kernel<<<256,256>>>(z2p,128,OFF_C2,1024);

    w0_kernel<<<NROWS/256,256>>>(w0_w,w0_b);
    stats_kernel<<<256,256>>>(w0p,8,OFF_W0,1024);
    w1_kernel<<<NROWS/256,256>>>(w1_w,w1_b,w0_g,w0_be);
    stats_kernel<<<256,256>>>(w1p,8,OFF_W1,1024);
    w2_kernel<<<NROWS/256,256>>>(w2_w,w2_b,w1_g,w1_be);
    stats_kernel<<<256,256>>>(w2p,16,OFF_W2,1024);

    agg_kernel<<<NB*NS,128>>>(g2,b2,w2_g,w2_be);
    lin_kernel<<<128,256>>>(lin_w,lin_b);
    stats_kernel<<<64,256>>>(yp,128,OFF_LIN,128);
    outy_kernel<<<dim3(32,4,NB),dim3(32,8)>>>(lg,lb,out);
}

// round 11
// speedup vs baseline: 1.2534x; 1.1896x over previous
#include <cuda_runtime.h>
#include <cuda_bf16.h>
#include <cstdint>
#include <cstddef>

#define NB 8
#define NN 4096
#define NS 1024
#define NK 32
#define NROWS (NB*NS*NK)      // 262144

#define OFF_C1 0
#define OFF_C2 64
#define OFF_W0 192
#define OFF_W1 200
#define OFF_W2 208
#define OFF_LIN 224
#define NSTAT 352
#define EPSBN 1e-5f

// ---------------- scratch ----------------
__device__ float  g_new_xyz[NB*NS*3];
__device__ int    g_nidx[NROWS];
__device__ float  g_off[NROWS*3];
__device__ float  g_Pt[NB*NN*64];
__device__ float  g_z1[(size_t)NROWS*64];
__device__ float  g_z2[(size_t)NROWS*128];
__device__ float  g_zw0[NROWS*8];
__device__ float  g_zw1[NROWS*8];
__device__ float  g_zw2[NROWS*16];
__device__ float  g_feats[(size_t)NB*NS*2048];
__device__ float  g_ypre[NB*NS*128];
__device__ double g_sum[NSTAT];
__device__ double g_sumsq[NSTAT];

// ---------------- helpers ----------------
__device__ __forceinline__ float2 bn_sf(int off,int c,double n,
                                        const float* __restrict__ gamma,
                                        const float* __restrict__ beta){
    double m  = g_sum[off+c]/n;
    double vv = g_sumsq[off+c]/n - m*m;
    float s = gamma[c]*rsqrtf((float)vv + EPSBN);
    float h = beta[c] - (float)m*s;
    return make_float2(s,h);
}

// ---------------- zero stats ----------------
__global__ void zero_stats_kernel(){
    int t=threadIdx.x;
    if (t<NSTAT){ g_sum[t]=0.0; g_sumsq[t]=0.0; }
}

// ---------------- FPS: one block per batch, redux + atomicMin argmax ----------
__global__ __launch_bounds__(1024) void fps_kernel(const float* __restrict__ xyz,
                                                   float* __restrict__ out){
    int b=blockIdx.x, t=threadIdx.x;
    const float* xb = xyz + b*3*NN;
    float px[4],py[4],pz[4],dist[4];
#pragma unroll
    for(int j=0;j<4;j++){
        int i=t+j*1024;
        px[j]=xb[i]; py[j]=xb[NN+i]; pz[j]=xb[2*NN+i];
        dist[j]=1e10f;
    }
    __shared__ float cx,cy,cz;
    __shared__ unsigned wmax[32];
    __shared__ unsigned mbits;
    __shared__ int idx_sh;
    int wid=t>>5, lane=t&31;

    if (t==0){
        cx=px[0]; cy=py[0]; cz=pz[0];
        g_new_xyz[(b*NS)*3+0]=px[0]; g_new_xyz[(b*NS)*3+1]=py[0]; g_new_xyz[(b*NS)*3+2]=pz[0];
        out[b*3072+0]=px[0]; out[b*3072+1024]=py[0]; out[b*3072+2048]=pz[0];
    }
    __syncthreads();

    for (int k=1;k<NS;k++){
        float lcx=cx,lcy=cy,lcz=cz;
        unsigned mymax=0u;
#pragma unroll
        for(int j=0;j<4;j++){
            float dx=px[j]-lcx, dy=py[j]-lcy, dz=pz[j]-lcz;
            float d=__fadd_rn(__fadd_rn(__fmul_rn(dx,dx),__fmul_rn(dy,dy)),__fmul_rn(dz,dz));
            dist[j]=fminf(dist[j],d);
            unsigned ub=__float_as_uint(dist[j]);   // dists >= 0: uint order == float order
            if(ub>mymax) mymax=ub;
        }
        mymax=__reduce_max_sync(0xffffffffu,mymax);
        if(lane==0) wmax[wid]=mymax;
        __syncthreads();
        if(wid==0){
            unsigned v=__reduce_max_sync(0xffffffffu,wmax[lane]);
            if(lane==0){ mbits=v; idx_sh=0x7FFFFFFF; }
        }
        __syncthreads();
        unsigned mb=mbits;
#pragma unroll
        for(int j=0;j<4;j++)
            if(__float_as_uint(dist[j])==mb) atomicMin(&idx_sh, t+j*1024);
        __syncthreads();
        int far=idx_sh;
        if((far&1023)==t){
            int j=far>>10;
            float fx=px[0],fy=py[0],fz=pz[0];
#pragma unroll
            for(int jj=1;jj<4;jj++){ if(j==jj){fx=px[jj];fy=py[jj];fz=pz[jj];} }
            cx=fx; cy=fy; cz=fz;
            g_new_xyz[(b*NS+k)*3+0]=fx; g_new_xyz[(b*NS+k)*3+1]=fy; g_new_xyz[(b*NS+k)*3+2]=fz;
            out[b*3072+k]=fx; out[b*3072+1024+k]=fy; out[b*3072+2048+k]=fz;
        }
        __syncthreads();
    }
}

// ---------------- transpose points [B,64,N] -> [B,N,64] ----------------
__global__ void transpose_kernel(const float* __restrict__ points){
    __shared__ float tile[32][33];
    int b=blockIdx.z, n0=blockIdx.x*32, c0=blockIdx.y*32;
    int tx=threadIdx.x, ty=threadIdx.y;
#pragma unroll
    for(int i=0;i<32;i+=8)
        tile[ty+i][tx]=points[b*64*NN+(c0+ty+i)*NN+n0+tx];
    __syncthreads();
#pragma unroll
    for(int i=0;i<32;i+=8)
        g_Pt[(b*NN+n0+ty+i)*64+c0+tx]=tile[tx][ty+i];
}

// ---------------- kNN: exact top-32 via 8-bit MSB radix select ----------------
__global__ __launch_bounds__(256) void knn_kernel(const float* __restrict__ xyz){
    int q=blockIdx.x, b=q>>10, t=threadIdx.x;
    const float* xb=xyz+b*3*NN;
    float qx=g_new_xyz[q*3], qy=g_new_xyz[q*3+1], qz=g_new_xyz[q*3+2];
    float q2=__fadd_rn(__fadd_rn(__fmul_rn(qx,qx),__fmul_rn(qy,qy)),__fmul_rn(qz,qz));

    unsigned dk[16];
#pragma unroll
    for(int j=0;j<16;j++){
        int i=j*256+t;
        float x=xb[i], y=xb[NN+i], z=xb[2*NN+i];
        float n2=__fadd_rn(__fadd_rn(__fmul_rn(x,x),__fmul_rn(y,y)),__fmul_rn(z,z));
        float dot=__fadd_rn(__fadd_rn(__fmul_rn(qx,x),__fmul_rn(qy,y)),__fmul_rn(qz,z));
        float d=__fadd_rn(__fadd_rn(__fmul_rn(-2.0f,dot),q2),n2);
        unsigned u=__float_as_uint(d);
        dk[j]=(u&0x80000000u)?~u:(u|0x80000000u);   // order-preserving transform
    }

    __shared__ unsigned hist[256];
    __shared__ unsigned sh_d, sh_cb;
    __shared__ unsigned cnt, tcnt;
    __shared__ unsigned ties[256];

    unsigned prefix=0, R=32;
#pragma unroll
    for(int shift=24;shift>=0;shift-=8){
        hist[t]=0;
        __syncthreads();
        unsigned mask_hi=(shift==24)?0u:(0xFFFFFFFFu<<(shift+8));
#pragma unroll
        for(int j=0;j<16;j++){
            if((dk[j]&mask_hi)==prefix)
                atomicAdd(&hist[(dk[j]>>shift)&0xFFu],1u);
        }
        __syncthreads();
        if(t<32){
            unsigned s=0;
#pragma unroll
            for(int i=0;i<8;i++) s+=hist[t*8+i];
            unsigned v=s;
#pragma unroll
            for(int o=1;o<32;o<<=1){ unsigned u=__shfl_up_sync(0xffffffffu,v,o); if(t>=o) v+=u; }
            unsigned cum=v-s;
            unsigned cand=0xFFFFFFFFu;
#pragma unroll
            for(int i=0;i<8;i++){
                unsigned h=hist[t*8+i];
                if(cand==0xFFFFFFFFu && cum+h>=R) cand=((unsigned)(t*8+i)<<16)|cum;
                cum+=h;
            }
#pragma unroll
            for(int o=16;o>0;o>>=1){ unsigned u=__shfl_down_sync(0xffffffffu,cand,o); if(u<cand)cand=u; }
            if(t==0){ sh_d=cand>>16; sh_cb=cand&0xFFFFu; }
        }
        __syncthreads();
        prefix|=sh_d<<shift;
        R-=sh_cb;
    }
    unsigned T=prefix;
    if(t==0){ cnt=0; tcnt=0; }
    __syncthreads();
#pragma unroll
    for(int j=0;j<16;j++){
        unsigned key=dk[j];
        unsigned idx=(unsigned)(j*256+t);
        if(key<T){
            unsigned p=atomicAdd(&cnt,1u);
            g_nidx[q*NK+p]=(int)idx;
        } else if(key==T){
            unsigned p=atomicAdd(&tcnt,1u);
            if(p<256u) ties[p]=idx;
        }
    }
    __syncthreads();
    if(t==0){
        unsigned n=cnt;
        unsigned L=tcnt<256u?tcnt:256u;
        for(unsigned r=0;r<R;r++){
            unsigned mi=0xFFFFFFFFu, mp=0;
            for(unsigned i=0;i<L;i++) if(ties[i]<mi){mi=ties[i];mp=i;}
            g_nidx[q*NK+n+r]=(int)mi;
            ties[mp]=0xFFFFFFFFu;
        }
    }
    __syncthreads();
    if(t<NK){
        int n=g_nidx[q*NK+t];
        g_off[(q*NK+t)*3+0]=xb[n]-qx;
        g_off[(q*NK+t)*3+1]=xb[NN+n]-qy;
        g_off[(q*NK+t)*3+2]=xb[2*NN+n]-qz;
    }
}

// ---------------- z1 = gather(P) . c1_w^T + c1_b ----------------
__global__ __launch_bounds__(128) void z1_kernel(const float* __restrict__ W,
                                                 const float* __restrict__ bias){
    __shared__ float Ws[64*64];
    __shared__ float bs[64];
    int t=threadIdx.x;
    for(int i=t;i<4096;i+=128) Ws[i]=W[i];
    if(t<64) bs[t]=bias[t];
    __syncthreads();

    int row=blockIdx.x*128+t;
    int b=row>>15;
    int n=g_nidx[row];
    const float4* src=(const float4*)(g_Pt+((size_t)(b<<12)+n)*64);
    float f[64];
#pragma unroll
    for(int i=0;i<16;i++){ float4 v=src[i]; f[4*i]=v.x; f[4*i+1]=v.y; f[4*i+2]=v.z; f[4*i+3]=v.w; }
    float4* dst=(float4*)(g_z1+(size_t)row*64);
    const float4* W4=(const float4*)Ws;
    for(int c4=0;c4<16;c4++){
        float a0=bs[4*c4],a1=bs[4*c4+1],a2=bs[4*c4+2],a3=bs[4*c4+3];
#pragma unroll
        for(int i=0;i<16;i++){
            float4 w0=W4[(4*c4+0)*16+i], w1=W4[(4*c4+1)*16+i];
            float4 w2=W4[(4*c4+2)*16+i], w3=W4[(4*c4+3)*16+i];
            a0=fmaf(f[4*i],w0.x,fmaf(f[4*i+1],w0.y,fmaf(f[4*i+2],w0.z,fmaf(f[4*i+3],w0.w,a0))));
            a1=fmaf(f[4*i],w1.x,fmaf(f[4*i+1],w1.y,fmaf(f[4*i+2],w1.z,fmaf(f[4*i+3],w1.w,a1))));
            a2=fmaf(f[4*i],w2.x,fmaf(f[4*i+1],w2.y,fmaf(f[4*i+2],w2.z,fmaf(f[4*i+3],w2.w,a2))));
            a3=fmaf(f[4*i],w3.x,fmaf(f[4*i+1],w3.y,fmaf(f[4*i+2],w3.z,fmaf(f[4*i+3],w3.w,a3))));
        }
        dst[c4]=make_float4(a0,a1,a2,a3);
    }
}

// ---------------- z2 = relu(bn1(z1)) . c2_w^T + c2_b ----------------
__global__ __launch_bounds__(128) void z2_kernel(const float* __restrict__ W,
                                                 const float* __restrict__ bias,
                                                 const float* __restrict__ gam,
                                                 const float* __restrict__ bet){
    __shared__ float Ws[128*64];
    __shared__ float bs[128];
    __shared__ float sc[64], sh[64];
    int t=threadIdx.x;
    for(int i=t;i<8192;i+=128) Ws[i]=W[i];
    bs[t]=bias[t];
    if(t<64){ float2 p=bn_sf(OFF_C1,t,262144.0,gam,bet); sc[t]=p.x; sh[t]=p.y; }
    __syncthreads();

    int row=blockIdx.x*128+t;
    const float4* src=(const float4*)(g_z1+(size_t)row*64);
    float a[64];
#pragma unroll
    for(int i=0;i<16;i++){
        float4 v=src[i];
        a[4*i]  =fmaxf(0.f,v.x*sc[4*i]  +sh[4*i]);
        a[4*i+1]=fmaxf(0.f,v.y*sc[4*i+1]+sh[4*i+1]);
        a[4*i+2]=fmaxf(0.f,v.z*sc[4*i+2]+sh[4*i+2]);
        a[4*i+3]=fmaxf(0.f,v.w*sc[4*i+3]+sh[4*i+3]);
    }
    float4* dst=(float4*)(g_z2+(size_t)row*128);
    const float4* W4=(const float4*)Ws;
    for(int c4=0;c4<32;c4++){
        float a0=bs[4*c4],a1=bs[4*c4+1],a2=bs[4*c4+2],a3=bs[4*c4+3];
#pragma unroll
        for(int i=0;i<16;i++){
            float4 w0=W4[(4*c4+0)*16+i], w1=W4[(4*c4+1)*16+i];
            float4 w2=W4[(4*c4+2)*16+i], w3=W4[(4*c4+3)*16+i];
            a0=fmaf(a[4*i],w0.x,fmaf(a[4*i+1],w0.y,fmaf(a[4*i+2],w0.z,fmaf(a[4*i+3],w0.w,a0))));
            a1=fmaf(a[4*i],w1.x,fmaf(a[4*i+1],w1.y,fmaf(a[4*i+2],w1.z,fmaf(a[4*i+3],w1.w,a1))));
            a2=fmaf(a[4*i],w2.x,fmaf(a[4*i+1],w2.y,fmaf(a[4*i+2],w2.z,fmaf(a[4*i+3],w2.w,a2))));
            a3=fmaf(a[4*i],w3.x,fmaf(a[4*i+1],w3.y,fmaf(a[4*i+2],w3.z,fmaf(a[4*i+3],w3.w,a3))));
        }
        dst[c4]=make_float4(a0,a1,a2,a3);
    }
}

// ---------------- WeightNet layers ----------------
__global__ __launch_bounds__(256) void w0_kernel(const float* __restrict__ W,
                                                 const float* __restrict__ bias){
    int r=blockIdx.x*256+threadIdx.x;
    float x=g_off[r*3], y=g_off[r*3+1], z=g_off[r*3+2];
#pragma unroll
    for(int c=0;c<8;c++)
        g_zw0[r*8+c]=fmaf(x,W[c*3],fmaf(y,W[c*3+1],fmaf(z,W[c*3+2],bias[c])));
}

__global__ __launch_bounds__(256) void w1_kernel(const float* __restrict__ W,
                                                 const float* __restrict__ bias,
                                                 const float* __restrict__ gam,
                                                 const float* __restrict__ bet){
    __shared__ float sc[8],sh[8];
    int t=threadIdx.x;
    if(t<8){ float2 p=bn_sf(OFF_W0,t,262144.0,gam,bet); sc[t]=p.x; sh[t]=p.y; }
    __syncthreads();
    int r=blockIdx.x*256+t;
    float a[8];
#pragma unroll
    for(int i=0;i<8;i++) a[i]=fmaxf(0.f,g_zw0[r*8+i]*sc[i]+sh[i]);
#pragma unroll
    for(int c=0;c<8;c++){
        float acc=bias[c];
#pragma unroll
        for(int i=0;i<8;i++) acc=fmaf(a[i],W[c*8+i],acc);
        g_zw1[r*8+c]=acc;
    }
}

__global__ __launch_bounds__(256) void w2_kernel(const float* __restrict__ W,
                                                 const float* __restrict__ bias,
                                                 const float* __restrict__ gam,
                                                 const float* __restrict__ bet){
    __shared__ float sc[8],sh[8];
    int t=threadIdx.x;
    if(t<8){ float2 p=bn_sf(OFF_W1,t,262144.0,gam,bet); sc[t]=p.x; sh[t]=p.y; }
    __syncthreads();
    int r=blockIdx.x*256+t;
    float a[8];
#pragma unroll
    for(int i=0;i<8;i++) a[i]=fmaxf(0.f,g_zw1[r*8+i]*sc[i]+sh[i]);
#pragma unroll
    for(int c=0;c<16;c++){
        float acc=bias[c];
#pragma unroll
        for(int i=0;i<8;i++) acc=fmaf(a[i],W[c*8+i],acc);
        g_zw2[r*16+c]=acc;
    }
}

// ---------------- aggregation: feats[p, c*16+w] = sum_k f*w ----------------
__global__ __launch_bounds__(128) void agg_kernel(const float* __restrict__ g2,
                                                  const float* __restrict__ b2,
                                                  const float* __restrict__ wg,
                                                  const float* __restrict__ wbe){
    __shared__ float wsh[32][16];
    __shared__ float s2s[128],h2s[128],sws[16],hws[16];
    int p=blockIdx.x, t=threadIdx.x;
    { float2 pr=bn_sf(OFF_C2,t,262144.0,g2,b2); s2s[t]=pr.x; h2s[t]=pr.y; }
    if(t<16){ float2 pr=bn_sf(OFF_W2,t,262144.0,wg,wbe); sws[t]=pr.x; hws[t]=pr.y; }
    __syncthreads();
    for(int i=t;i<512;i+=128){
        int k=i>>4, w=i&15;
        float v=g_zw2[(p*32+k)*16+w];
        wsh[k][w]=fmaxf(0.f,v*sws[w]+hws[w]);
    }
    __syncthreads();
    float s2=s2s[t], h2=h2s[t];
    float acc[16];
#pragma unroll
    for(int w=0;w<16;w++) acc[w]=0.f;
    for(int k=0;k<32;k++){
        float fv=fmaxf(0.f,g_z2[((size_t)(p*32+k))*128+t]*s2+h2);
#pragma unroll
        for(int w=0;w<16;w++) acc[w]=fmaf(fv,wsh[k][w],acc[w]);
    }
    float4* d=(float4*)(g_feats+(size_t)p*2048+t*16);
#pragma unroll
    for(int w4=0;w4<4;w4++)
        d[w4]=make_float4(acc[4*w4],acc[4*w4+1],acc[4*w4+2],acc[4*w4+3]);
}

// ---------------- final GEMM: ypre = feats @ lin_w^T + lin_b ----------------
// 64x128 tile per block; conflict-free split-column fragments.
__global__ __launch_bounds__(256) void lin_kernel(const float* __restrict__ W,
                                                  const float* __restrict__ bias){
    __shared__ float As[32][68];   // [k][m]
    __shared__ float Bs[32][132];  // [k][n]
    int t=threadIdx.x;
    int row0=blockIdx.x*64;
    int lk=(t&7)*4;
    int lr=t>>3;
    int tr=t>>4;          // 0..15 -> rows tr*4..tr*4+3
    int tc=t&15;          // 0..15 -> cols {tc*4..+3, 64+tc*4..+3}

    const float* pA0=g_feats+(size_t)(row0+lr)*2048+lk;
    const float* pA1=g_feats+(size_t)(row0+lr+32)*2048+lk;
    const float* pB0=W+(size_t)lr*2048+lk;
    const float* pB1=W+(size_t)(lr+32)*2048+lk;
    const float* pB2=W+(size_t)(lr+64)*2048+lk;
    const float* pB3=W+(size_t)(lr+96)*2048+lk;

    float4 a0=*(const float4*)pA0, a1=*(const float4*)pA1;
    float4 b0=*(const float4*)pB0, b1=*(const float4*)pB1;
    float4 b2=*(const float4*)pB2, b3=*(const float4*)pB3;

    float acc[4][8];
#pragma unroll
    for(int j=0;j<4;j++)
#pragma unroll
        for(int jj=0;jj<8;jj++) acc[j][jj]=0.f;

    for(int k0=0;k0<2048;k0+=32){
        As[lk+0][lr]=a0.x; As[lk+1][lr]=a0.y; As[lk+2][lr]=a0.z; As[lk+3][lr]=a0.w;
        As[lk+0][lr+32]=a1.x; As[lk+1][lr+32]=a1.y; As[lk+2][lr+32]=a1.z; As[lk+3][lr+32]=a1.w;
        Bs[lk+0][lr]=b0.x; Bs[lk+1][lr]=b0.y; Bs[lk+2][lr]=b0.z; Bs[lk+3][lr]=b0.w;
        Bs[lk+0][lr+32]=b1.x; Bs[lk+1][lr+32]=b1.y; Bs[lk+2][lr+32]=b1.z; Bs[lk+3][lr+32]=b1.w;
        Bs[lk+0][lr+64]=b2.x; Bs[lk+1][lr+64]=b2.y; Bs[lk+2][lr+64]=b2.z; Bs[lk+3][lr+64]=b2.w;
        Bs[lk+0][lr+96]=b3.x; Bs[lk+1][lr+96]=b3.y; Bs[lk+2][lr+96]=b3.z; Bs[lk+3][lr+96]=b3.w;
        __syncthreads();
        if(k0+32<2048){
            int o=k0+32;
            a0=*(const float4*)(pA0+o); a1=*(const float4*)(pA1+o);
            b0=*(const float4*)(pB0+o); b1=*(const float4*)(pB1+o);
            b2=*(const float4*)(pB2+o); b3=*(const float4*)(pB3+o);
        }
#pragma unroll
        for(int kk=0;kk<32;kk++){
            float4 ra =*(const float4*)&As[kk][tr*4];
            float4 rb0=*(const float4*)&Bs[kk][tc*4];
            float4 rb1=*(const float4*)&Bs[kk][64+tc*4];
            float ar[4]={ra.x,ra.y,ra.z,ra.w};
            float br[8]={rb0.x,rb0.y,rb0.z,rb0.w,rb1.x,rb1.y,rb1.z,rb1.w};
#pragma unroll
            for(int j=0;j<4;j++)
#pragma unroll
                for(int jj=0;jj<8;jj++) acc[j][jj]=fmaf(ar[j],br[jj],acc[j][jj]);
        }
        __syncthreads();
    }
#pragma unroll
    for(int j=0;j<4;j++){
#pragma unroll
        for(int jj=0;jj<4;jj++)
            g_ypre[(size_t)(row0+tr*4+j)*128+tc*4+jj]=acc[j][jj]+bias[tc*4+jj];
#pragma unroll
        for(int jj=0;jj<4;jj++)
            g_ypre[(size_t)(row0+tr*4+j)*128+64+tc*4+jj]=acc[j][jj+4]+bias[64+tc*4+jj];
    }
}

// ---------------- generic channel stats (4-way ILP) ----------------
// Requires (rpb/rstep) % 4 == 0 for all call sites (holds: 256,512,32,64,64).
__global__ __launch_bounds__(256) void stats_kernel(const float* __restrict__ data,
                                                    int cols,int off,int rpb){
    int t=threadIdx.x;
    int ch=t%cols;
    int rstep=256/cols;
    double s0=0.0,s1=0.0,s2=0.0,s3=0.0;
    double q0=0.0,q1=0.0,q2=0.0,q3=0.0;
    size_t base=(size_t)blockIdx.x*rpb;
    int r0=t/cols;
    for(int r=r0;r<rpb;r+=4*rstep){
        float v0=data[(base+r)*(size_t)cols+ch];
        float v1=data[(base+r+rstep)*(size_t)cols+ch];
        float v2=data[(base+r+2*rstep)*(size_t)cols+ch];
        float v3=data[(base+r+3*rstep)*(size_t)cols+ch];
        s0+=v0; q0+=(double)v0*v0;
        s1+=v1; q1+=(double)v1*v1;
        s2+=v2; q2+=(double)v2*v2;
        s3+=v3; q3+=(double)v3*v3;
    }
    atomicAdd(&g_sum[off+ch],(s0+s1)+(s2+s3));
    atomicAdd(&g_sumsq[off+ch],(q0+q1)+(q2+q3));
}

// ---------------- output: y = relu(bn(ypre)) transposed ----------------
__global__ void outy_kernel(const float* __restrict__ lg,
                            const float* __restrict__ lb,
                            float* __restrict__ out){
    __shared__ float tile[32][33];
    __shared__ float s[32],h[32];
    int b=blockIdx.z, s0=blockIdx.x*32, c0=blockIdx.y*32;
    int tx=threadIdx.x, ty=threadIdx.y;
    if(ty==0){ float2 p=bn_sf(OFF_LIN,c0+tx,8192.0,lg,lb); s[tx]=p.x; h[tx]=p.y; }
    __syncthreads();
#pragma unroll
    for(int i=0;i<32;i+=8){
        float v=g_ypre[(size_t)(b*1024+s0+ty+i)*128+c0+tx];
        tile[ty+i][tx]=fmaxf(0.f,v*s[tx]+h[tx]);
    }
    __syncthreads();
    float* y=out+24576;
#pragma unroll
    for(int i=0;i<32;i+=8)
        y[(size_t)b*131072+(c0+ty+i)*1024+s0+tx]=tile[tx][ty+i];
}

// ---------------- launch ----------------
extern "C" void kernel_launch(void* const* d_in, const int* in_sizes, int n_in,
                              void* d_out, int out_size){
    const float* xyz   =(const float*)d_in[0];
    const float* points=(const float*)d_in[1];
    const float* c1_w=(const float*)d_in[2];  const float* c1_b=(const float*)d_in[3];
    const float* g1  =(const float*)d_in[4];  const float* b1  =(const float*)d_in[5];
    const float* c2_w=(const float*)d_in[6];  const float* c2_b=(const float*)d_in[7];
    const float* g2  =(const float*)d_in[8];  const float* b2  =(const float*)d_in[9];
    const float* w0_w=(const float*)d_in[10]; const float* w0_b=(const float*)d_in[11];
    const float* w0_g=(const float*)d_in[12]; const float* w0_be=(const float*)d_in[13];
    const float* w1_w=(const float*)d_in[14]; const float* w1_b=(const float*)d_in[15];
    const float* w1_g=(const float*)d_in[16]; const float* w1_be=(const float*)d_in[17];
    const float* w2_w=(const float*)d_in[18]; const float* w2_b=(const float*)d_in[19];
    const float* w2_g=(const float*)d_in[20]; const float* w2_be=(const float*)d_in[21];
    const float* lin_w=(const float*)d_in[22];const float* lin_b=(const float*)d_in[23];
    const float* lg  =(const float*)d_in[24]; const float* lb  =(const float*)d_in[25];
    float* out=(float*)d_out;

    float *z1p,*z2p,*w0p,*w1p,*w2p,*yp;
    cudaGetSymbolAddress((void**)&z1p,g_z1);
    cudaGetSymbolAddress((void**)&z2p,g_z2);
    cudaGetSymbolAddress((void**)&w0p,g_zw0);
    cudaGetSymbolAddress((void**)&w1p,g_zw1);
    cudaGetSymbolAddress((void**)&w2p,g_zw2);
    cudaGetSymbolAddress((void**)&yp, g_ypre);

    zero_stats_kernel<<<1,512>>>();
    fps_kernel<<<NB,1024>>>(xyz,out);
    transpose_kernel<<<dim3(NN/32,2,NB),dim3(32,8)>>>(points);
    knn_kernel<<<NB*NS,256>>>(xyz);

    z1_kernel<<<NROWS/128,128>>>(c1_w,c1_b);
    stats_kernel<<<256,256>>>(z1p,64,OFF_C1,1024);
    z2_kernel<<<NROWS/128,128>>>(c2_w,c2_b,g1,b1);
    stats_kernel<<<256,256>>>(z2p,128,OFF_C2,1024);

    w0_kernel<<<NROWS/256,256>>>(w0_w,w0_b);
    stats_kernel<<<256,256>>>(w0p,8,OFF_W0,1024);
    w1_kernel<<<NROWS/256,256>>>(w1_w,w1_b,w0_g,w0_be);
    stats_kernel<<<256,256>>>(w1p,8,OFF_W1,1024);
    w2_kernel<<<NROWS/256,256>>>(w2_w,w2_b,w1_g,w1_be);
    stats_kernel<<<256,256>>>(w2p,16,OFF_W2,1024);

    agg_kernel<<<NB*NS,128>>>(g2,b2,w2_g,w2_be);
    lin_kernel<<<128,256>>>(lin_w,lin_b);
    stats_kernel<<<64,256>>>(yp,128,OFF_LIN,128);
    outy_kernel<<<dim3(32,4,NB),dim3(32,8)>>>(lg,lb,out);
}